// round 15
// baseline (speedup 1.0000x reference)
#include <cuda_runtime.h>
#include <cstdint>

// Problem constants
#define BB   32
#define TT   256
#define FF   224
#define EE   32
#define NHH  4
#define DHH  64
#define DD   256
#define HH   256
#define ROWS (BB*TT)   // 8192

// ---------------- scratch (static device globals; no allocation) ------------
__device__ float g_x [ROWS*DD];
__device__ float g_xn[ROWS*DD];
__device__ float g_g0[ROWS*HH];
__device__ float g_g1[ROWS*HH];
__device__ float g_g2[ROWS*HH];
__device__ float g_g3[ROWS*HH];
__device__ float g_h [ROWS*HH];
__device__ float g_bs[BB*NHH*TT];
__device__ float g_Mt[BB*NHH*TT];

__device__ __forceinline__ float* bufsel(int s) {
    switch (s) {
        case 0: return g_x;
        case 1: return g_xn;
        default: return g_h;
    }
}
#define SEL_X  0
#define SEL_XN 1
#define SEL_H  2

__device__ __forceinline__ void cp16(void* s, const void* g) {
    uint32_t sa = (uint32_t)__cvta_generic_to_shared(s);
    asm volatile("cp.async.cg.shared.global [%0], [%1], 16;"
                 :: "r"(sa), "l"(g) : "memory");
}
#define CP_COMMIT() asm volatile("cp.async.commit_group;" ::: "memory")
#define CP_WAIT1()  asm volatile("cp.async.wait_group 1;" ::: "memory")
#define CP_WAIT0()  asm volatile("cp.async.wait_group 0;" ::: "memory")

// ---------------- input assembly + LayerNorm 0 --------------------------------
__global__ void build_ln(const float* __restrict__ X,
                         const int*   __restrict__ dyad,
                         const float* __restrict__ embed,
                         const float* __restrict__ gam,
                         const float* __restrict__ bet) {
    int row = blockIdx.x;
    int t   = threadIdx.x;
    int b   = row / TT;
    float v;
    if (t < FF) v = X[row*FF + t];
    else        v = embed[dyad[b]*EE + (t - FF)];
    g_x[row*DD + t] = v;

    float s = v, s2 = v*v;
    #pragma unroll
    for (int off = 16; off; off >>= 1) {
        s  += __shfl_xor_sync(0xffffffffu, s,  off);
        s2 += __shfl_xor_sync(0xffffffffu, s2, off);
    }
    __shared__ float a1[8], a2[8];
    __shared__ float smu, srs;
    if ((t & 31) == 0) { a1[t >> 5] = s; a2[t >> 5] = s2; }
    __syncthreads();
    if (t == 0) {
        float u = 0.f, u2 = 0.f;
        #pragma unroll
        for (int i = 0; i < 8; i++) { u += a1[i]; u2 += a2[i]; }
        float mu  = u  * (1.0f/DD);
        float var = u2 * (1.0f/DD) - mu*mu;
        smu = mu;
        srs = rsqrtf(var + 1e-5f);
    }
    __syncthreads();
    g_xn[row*DD + t] = (v - smu) * srs * gam[t] + bet[t];
}

// ---------------- LayerNorm ----------------------------------------------------
__global__ void ln_kernel(const float* __restrict__ gam,
                          const float* __restrict__ bet) {
    int row = blockIdx.x, t = threadIdx.x;
    float x  = g_x[row*DD + t];
    float s  = x, s2 = x*x;
    #pragma unroll
    for (int off = 16; off; off >>= 1) {
        s  += __shfl_xor_sync(0xffffffffu, s,  off);
        s2 += __shfl_xor_sync(0xffffffffu, s2, off);
    }
    __shared__ float a1[8], a2[8];
    __shared__ float smu, srs;
    if ((t & 31) == 0) { a1[t >> 5] = s; a2[t >> 5] = s2; }
    __syncthreads();
    if (t == 0) {
        float u = 0.f, u2 = 0.f;
        #pragma unroll
        for (int i = 0; i < 8; i++) { u += a1[i]; u2 += a2[i]; }
        float mu  = u  * (1.0f/DD);
        float var = u2 * (1.0f/DD) - mu*mu;
        smu = mu;
        srs = rsqrtf(var + 1e-5f);
    }
    __syncthreads();
    g_xn[row*DD + t] = (x - smu) * srs * gam[t] + bet[t];
}

// ---------------- tf32 mma helper ----------------------------------------------
__device__ __forceinline__ void mma_tf32(float (&d)[4],
                                         const uint32_t (&a)[4],
                                         const uint32_t (&b)[2]) {
    asm volatile(
        "mma.sync.aligned.m16n8k8.row.col.f32.tf32.tf32.f32 "
        "{%0,%1,%2,%3}, {%4,%5,%6,%7}, {%8,%9}, {%0,%1,%2,%3};"
        : "+f"(d[0]), "+f"(d[1]), "+f"(d[2]), "+f"(d[3])
        : "r"(a[0]), "r"(a[1]), "r"(a[2]), "r"(a[3]),
          "r"(b[0]), "r"(b[1]));
}

// ---------------- tf32 GEMM: 128x128 tile, BK=32, cp.async double buffer -------
#define BK   32
#define AST  36
#define BST  136
#define GEMM_SMEM ((2*128*AST + 2*BK*BST) * 4)

__global__ void __launch_bounds__(256, 2) gemm_mma(
    int aSel,
    const float* __restrict__ W0, const float* __restrict__ W1,
    const float* __restrict__ W2, const float* __restrict__ W3,
    int mode)
{
    extern __shared__ uint32_t smg[];
    uint32_t* smA = smg;
    uint32_t* smB = smg + 2*128*AST;

    int tid  = threadIdx.x;
    int wid  = tid >> 5;
    int lane = tid & 31;
    int grp  = lane >> 2;
    int tig  = lane & 3;

    int w  = blockIdx.x >> 1;
    int nt = blockIdx.x & 1;
    int colBase = nt * 128;
    int rowBase = blockIdx.y * 128;
    const float* Wsel = (w==0) ? W0 : (w==1) ? W1 : (w==2) ? W2 : W3;
    const float* A    = bufsel(aSel) + (size_t)rowBase * DD;

    int warpM = wid >> 1;
    int warpN = wid & 1;

    float acc[2][8][4];
    #pragma unroll
    for (int i = 0; i < 2; i++)
        #pragma unroll
        for (int j = 0; j < 8; j++)
            #pragma unroll
            for (int q = 0; q < 4; q++) acc[i][j][q] = 0.f;

    auto loadT = [&](int buf, int k0) {
        uint32_t* Ab = smA + buf*(128*AST);
        uint32_t* Bb = smB + buf*(BK*BST);
        #pragma unroll
        for (int i = 0; i < 4; i++) {
            int ch = tid + i*256;
            int r  = ch >> 3, cq = (ch & 7) * 4;
            cp16(Ab + r*AST + cq, A + (size_t)r*DD + k0 + cq);
        }
        #pragma unroll
        for (int i = 0; i < 4; i++) {
            int ch = tid + i*256;
            int rb = ch >> 5, cq = (ch & 31) * 4;
            cp16(Bb + rb*BST + cq, Wsel + (size_t)(k0 + rb)*HH + colBase + cq);
        }
    };

    loadT(0, 0);  CP_COMMIT();
    loadT(1, BK); CP_COMMIT();

    const int KI = DD / BK;
    #pragma unroll
    for (int i = 0; i < KI; i++) {
        CP_WAIT1();
        __syncthreads();
        int buf = i & 1;
        uint32_t* Ab = smA + buf*(128*AST);
        uint32_t* Bb = smB + buf*(BK*BST);

        #pragma unroll
        for (int ks = 0; ks < 4; ks++) {
            uint32_t afr[2][4];
            #pragma unroll
            for (int mt = 0; mt < 2; mt++) {
                int r = warpM*32 + mt*16 + grp;
                int c = ks*8 + tig;
                afr[mt][0] = Ab[r*AST + c];
                afr[mt][1] = Ab[(r+8)*AST + c];
                afr[mt][2] = Ab[r*AST + c + 4];
                afr[mt][3] = Ab[(r+8)*AST + c + 4];
            }
            uint32_t bfr[8][2];
            #pragma unroll
            for (int nt2 = 0; nt2 < 8; nt2++) {
                int c = warpN*64 + nt2*8 + grp;
                bfr[nt2][0] = Bb[(ks*8 + tig)*BST + c];
                bfr[nt2][1] = Bb[(ks*8 + tig + 4)*BST + c];
            }
            #pragma unroll
            for (int mt = 0; mt < 2; mt++)
                #pragma unroll
                for (int nt2 = 0; nt2 < 8; nt2++)
                    mma_tf32(acc[mt][nt2], afr[mt], bfr[nt2]);
        }
        __syncthreads();
        if (i + 2 < KI) loadT(buf, (i + 2) * BK);
        CP_COMMIT();
    }

    float* C = (w == 0) ? g_g0 : (w == 1) ? g_g1 : (w == 2) ? g_g2 : g_g3;
    bool scaleK = (mode == 0) && (w == 1);
    bool sig    = (mode == 0) && (w == 3);

    #pragma unroll
    for (int mt = 0; mt < 2; mt++) {
        #pragma unroll
        for (int nt2 = 0; nt2 < 8; nt2++) {
            float v[4] = {acc[mt][nt2][0], acc[mt][nt2][1],
                          acc[mt][nt2][2], acc[mt][nt2][3]};
            if (scaleK) {
                #pragma unroll
                for (int q = 0; q < 4; q++) v[q] *= 0.125f;
            } else if (sig) {
                #pragma unroll
                for (int q = 0; q < 4; q++)
                    v[q] = __fdividef(1.f, 1.f + __expf(-v[q]));
            }
            int r0 = rowBase + warpM*32 + mt*16 + grp;
            int c0 = colBase + warpN*64 + nt2*8 + tig*2;
            *(float2*)(C + (size_t)r0 * HH + c0)     = make_float2(v[0], v[1]);
            *(float2*)(C + (size_t)(r0+8) * HH + c0) = make_float2(v[2], v[3]);
        }
    }
}

// ---------------- res GEMM: 128x64 tile (256 CTAs), residual accumulate --------
#define BST2 72
#define GEMM2_SMEM ((2*128*AST + 2*BK*BST2) * 4)

__global__ void __launch_bounds__(256, 2) gemm_res64(const float* __restrict__ Wp)
{
    extern __shared__ uint32_t smg[];
    uint32_t* smA = smg;
    uint32_t* smB = smg + 2*128*AST;

    int tid  = threadIdx.x;
    int wid  = tid >> 5;
    int lane = tid & 31;
    int grp  = lane >> 2;
    int tig  = lane & 3;

    int colBase = blockIdx.x * 64;
    int rowBase = blockIdx.y * 128;
    const float* A = g_h + (size_t)rowBase * HH;

    int warpM = wid >> 1;
    int warpN = wid & 1;

    float acc[2][4][4];
    #pragma unroll
    for (int i = 0; i < 2; i++)
        #pragma unroll
        for (int j = 0; j < 4; j++)
            #pragma unroll
            for (int q = 0; q < 4; q++) acc[i][j][q] = 0.f;

    auto loadT = [&](int buf, int k0) {
        uint32_t* Ab = smA + buf*(128*AST);
        uint32_t* Bb = smB + buf*(BK*BST2);
        #pragma unroll
        for (int i = 0; i < 4; i++) {
            int ch = tid + i*256;
            int r  = ch >> 3, cq = (ch & 7) * 4;
            cp16(Ab + r*AST + cq, A + (size_t)r*HH + k0 + cq);
        }
        #pragma unroll
        for (int i = 0; i < 2; i++) {
            int ch = tid + i*256;
            int rb = ch >> 4, cq = (ch & 15) * 4;
            cp16(Bb + rb*BST2 + cq, Wp + (size_t)(k0 + rb)*DD + colBase + cq);
        }
    };

    loadT(0, 0);  CP_COMMIT();
    loadT(1, BK); CP_COMMIT();

    const int KI = HH / BK;
    #pragma unroll
    for (int i = 0; i < KI; i++) {
        CP_WAIT1();
        __syncthreads();
        int buf = i & 1;
        uint32_t* Ab = smA + buf*(128*AST);
        uint32_t* Bb = smB + buf*(BK*BST2);

        #pragma unroll
        for (int ks = 0; ks < 4; ks++) {
            uint32_t afr[2][4];
            #pragma unroll
            for (int mt = 0; mt < 2; mt++) {
                int r = warpM*32 + mt*16 + grp;
                int c = ks*8 + tig;
                afr[mt][0] = Ab[r*AST + c];
                afr[mt][1] = Ab[(r+8)*AST + c];
                afr[mt][2] = Ab[r*AST + c + 4];
                afr[mt][3] = Ab[(r+8)*AST + c + 4];
            }
            uint32_t bfr[4][2];
            #pragma unroll
            for (int nt2 = 0; nt2 < 4; nt2++) {
                int c = warpN*32 + nt2*8 + grp;
                bfr[nt2][0] = Bb[(ks*8 + tig)*BST2 + c];
                bfr[nt2][1] = Bb[(ks*8 + tig + 4)*BST2 + c];
            }
            #pragma unroll
            for (int mt = 0; mt < 2; mt++)
                #pragma unroll
                for (int nt2 = 0; nt2 < 4; nt2++)
                    mma_tf32(acc[mt][nt2], afr[mt], bfr[nt2]);
        }
        __syncthreads();
        if (i + 2 < KI) loadT(buf, (i + 2) * BK);
        CP_COMMIT();
    }

    #pragma unroll
    for (int mt = 0; mt < 2; mt++) {
        #pragma unroll
        for (int nt2 = 0; nt2 < 4; nt2++) {
            int r0 = rowBase + warpM*32 + mt*16 + grp;
            int c0 = colBase + warpN*32 + nt2*8 + tig*2;
            float* p0 = g_x + (size_t)r0 * DD + c0;
            float* p1 = g_x + (size_t)(r0+8) * DD + c0;
            float2 o0 = *(const float2*)p0;
            float2 o1 = *(const float2*)p1;
            o0.x += acc[mt][nt2][0]; o0.y += acc[mt][nt2][1];
            o1.x += acc[mt][nt2][2]; o1.y += acc[mt][nt2][3];
            *(float2*)p0 = o0;
            *(float2*)p1 = o1;
        }
    }
}

// ---------------- fused gate preact + decay precompute -----------------------
__global__ void __launch_bounds__(256) gates_pre(const float* __restrict__ Wi,
                                                 const float* __restrict__ Wf,
                                                 const float* __restrict__ bi,
                                                 const float* __restrict__ bf) {
    __shared__ float wi_s[256], wf_s[256];
    __shared__ float sx[256][33];
    __shared__ double wsum[8];
    __shared__ float  wmax[8];

    int bh = blockIdx.x;
    int b = bh >> 2, nh = bh & 3;
    int tid = threadIdx.x;
    int lane = tid & 31, wid = tid >> 5;

    wi_s[tid] = Wi[tid*NHH + nh];
    wf_s[tid] = Wf[tid*NHH + nh];

    float ip = 0.f, fp = 0.f;
    for (int kc = 0; kc < 8; kc++) {
        __syncthreads();
        #pragma unroll
        for (int j = 0; j < 32; j++) {
            int idx = j*256 + tid;
            int r = idx >> 5, c = idx & 31;
            sx[r][c] = g_xn[(size_t)(b*TT + r)*DD + kc*32 + c];
        }
        __syncthreads();
        #pragma unroll
        for (int c = 0; c < 32; c++) {
            float x = sx[tid][c];
            ip = fmaf(x, wi_s[kc*32 + c], ip);
            fp = fmaf(x, wf_s[kc*32 + c], fp);
        }
    }
    ip += bi[nh];
    fp += bf[nh];

    double v = (double)fp;
    #pragma unroll
    for (int off = 1; off < 32; off <<= 1) {
        double u = __shfl_up_sync(0xffffffffu, v, off);
        if (lane >= off) v += u;
    }
    if (lane == 31) wsum[wid] = v;
    __syncthreads();
    if (tid < 32) {
        double t = (tid < 8) ? wsum[tid] : 0.0;
        #pragma unroll
        for (int off = 1; off < 8; off <<= 1) {
            double u = __shfl_up_sync(0xffffffffu, t, off);
            if (lane >= off) t += u;
        }
        if (tid < 8) wsum[tid] = t;
    }
    __syncthreads();
    double cumF = v + ((wid > 0) ? wsum[wid-1] : 0.0);
    float bt = (float)((double)ip - cumF);

    float mv = bt;
    #pragma unroll
    for (int off = 1; off < 32; off <<= 1) {
        float u = __shfl_up_sync(0xffffffffu, mv, off);
        if (lane >= off) mv = fmaxf(mv, u);
    }
    if (lane == 31) wmax[wid] = mv;
    __syncthreads();
    if (tid < 32) {
        float t = (tid < 8) ? wmax[tid] : -3.0e38f;
        #pragma unroll
        for (int off = 1; off < 8; off <<= 1) {
            float u = __shfl_up_sync(0xffffffffu, t, off);
            if (lane >= off) t = fmaxf(t, u);
        }
        if (tid < 8) wmax[tid] = t;
    }
    __syncthreads();
    float Mv = mv;
    if (wid > 0) Mv = fmaxf(Mv, wmax[wid-1]);
    Mv = fmaxf(Mv, 0.f);

    g_bs[bh*TT + tid] = bt;
    g_Mt[bh*TT + tid] = Mv;
}

// ---------------- parallel mLSTM attention (P aliases Ks: 3 smem tiles) -------
// grid 512 linear, work-descending: rt = 3 - (bid>>7). 52 KB smem -> 4 CTAs/SM.
#define PST 68
#define ATTN_SMEM (3*64*PST*4)

__global__ void __launch_bounds__(128) mlstm_attn() {
    extern __shared__ uint32_t smattn[];
    uint32_t (*Qs)[PST] = (uint32_t(*)[PST])(smattn);
    uint32_t (*Ks)[PST] = (uint32_t(*)[PST])(smattn + 64*PST);
    uint32_t (*Vs)[PST] = (uint32_t(*)[PST])(smattn + 2*64*PST);
    uint32_t (*Ps)[PST] = Ks;   // P overwrites Ks after S-compute (Ks dead)
    __shared__ float sb[64];

    int bid = blockIdx.x;
    int rt  = 3 - (bid >> 7);
    int bh  = bid & 127;
    int b = bh >> 2, nh = bh & 3;
    int tid  = threadIdx.x;
    int w    = tid >> 5;
    int lane = tid & 31;
    int grp  = lane >> 2;
    int tig  = lane & 3;
    int t0 = rt * 64;

    size_t rowBase = (size_t)(b*TT) * HH + nh*DHH;

    #pragma unroll
    for (int i = 0; i < 8; i++) {
        int idx = i*128 + tid;
        int r = idx >> 4, c = (idx & 15) * 4;
        cp16(&Qs[r][c], &g_g0[rowBase + (size_t)(t0 + r)*HH + c]);
    }
    float mrow0 = g_Mt[bh*TT + t0 + 16*w + grp];
    float mrow1 = g_Mt[bh*TT + t0 + 16*w + grp + 8];

    float numO[8][4];
    #pragma unroll
    for (int j = 0; j < 8; j++)
        #pragma unroll
        for (int q = 0; q < 4; q++) numO[j][q] = 0.f;
    float dsp0 = 0.f, dsp1 = 0.f;

    for (int jt = 0; jt <= rt; jt++) {
        int s0 = jt * 64;
        __syncthreads();    // prior-iter P@V reads of Ks/Vs complete before rewrite
        #pragma unroll
        for (int i = 0; i < 8; i++) {
            int idx = i*128 + tid;
            int r = idx >> 4, c = (idx & 15) * 4;
            cp16(&Ks[r][c], &g_g1[rowBase + (size_t)(s0 + r)*HH + c]);
            cp16(&Vs[r][c], &g_g2[rowBase + (size_t)(s0 + r)*HH + c]);
        }
        if (tid < 64) sb[tid] = g_bs[bh*TT + s0 + tid];
        CP_COMMIT();
        CP_WAIT0();
        __syncthreads();

        float accS[8][4];
        #pragma unroll
        for (int j = 0; j < 8; j++)
            #pragma unroll
            for (int q = 0; q < 4; q++) accS[j][q] = 0.f;
        #pragma unroll
        for (int ks = 0; ks < 8; ks++) {
            uint32_t a[4];
            a[0] = Qs[16*w + grp    ][8*ks + tig];
            a[1] = Qs[16*w + grp + 8][8*ks + tig];
            a[2] = Qs[16*w + grp    ][8*ks + tig + 4];
            a[3] = Qs[16*w + grp + 8][8*ks + tig + 4];
            #pragma unroll
            for (int nt = 0; nt < 8; nt++) {
                uint32_t bb[2];
                bb[0] = Ks[8*nt + grp][8*ks + tig];
                bb[1] = Ks[8*nt + grp][8*ks + tig + 4];
                mma_tf32(accS[nt], a, bb);
            }
        }
        __syncthreads();    // all warps finished reading Ks before P overwrites it

        int t_r0 = t0 + 16*w + grp;
        int t_r1 = t_r0 + 8;
        #pragma unroll
        for (int nt = 0; nt < 8; nt++) {
            int cl = nt*8 + tig*2;
            int s_c = s0 + cl;
            float b0 = sb[cl], b1 = sb[cl+1];
            float w00 = __expf(b0 - mrow0), w01 = __expf(b1 - mrow0);
            float w10 = __expf(b0 - mrow1), w11 = __expf(b1 - mrow1);
            if (jt == rt) {
                if (s_c     > t_r0) w00 = 0.f;
                if (s_c + 1 > t_r0) w01 = 0.f;
                if (s_c     > t_r1) w10 = 0.f;
                if (s_c + 1 > t_r1) w11 = 0.f;
            }
            float p00 = accS[nt][0]*w00, p01 = accS[nt][1]*w01;
            float p10 = accS[nt][2]*w10, p11 = accS[nt][3]*w11;
            dsp0 += p00 + p01;
            dsp1 += p10 + p11;
            Ps[16*w + grp    ][cl]   = __float_as_uint(p00);
            Ps[16*w + grp    ][cl+1] = __float_as_uint(p01);
            Ps[16*w + grp + 8][cl]   = __float_as_uint(p10);
            Ps[16*w + grp + 8][cl+1] = __float_as_uint(p11);
        }
        __syncwarp();   // warp w reads only its own 16 P rows

        #pragma unroll
        for (int ks = 0; ks < 8; ks++) {
            uint32_t a[4];
            a[0] = Ps[16*w + grp    ][8*ks + tig];
            a[1] = Ps[16*w + grp + 8][8*ks + tig];
            a[2] = Ps[16*w + grp    ][8*ks + tig + 4];
            a[3] = Ps[16*w + grp + 8][8*ks + tig + 4];
            #pragma unroll
            for (int nt = 0; nt < 8; nt++) {
                uint32_t bb[2];
                bb[0] = Vs[8*ks + tig    ][8*nt + grp];
                bb[1] = Vs[8*ks + tig + 4][8*nt + grp];
                mma_tf32(numO[nt], a, bb);
            }
        }
    }

    dsp0 += __shfl_xor_sync(0xffffffffu, dsp0, 1);
    dsp0 += __shfl_xor_sync(0xffffffffu, dsp0, 2);
    dsp1 += __shfl_xor_sync(0xffffffffu, dsp1, 1);
    dsp1 += __shfl_xor_sync(0xffffffffu, dsp1, 2);
    float inv0 = __fdividef(1.0f, fmaxf(fabsf(dsp0), 1.0f));
    float inv1 = __fdividef(1.0f, fmaxf(fabsf(dsp1), 1.0f));

    int t_r0 = t0 + 16*w + grp;
    #pragma unroll
    for (int nt = 0; nt < 8; nt++) {
        int c = nt*8 + tig*2;
        size_t a0 = rowBase + (size_t)t_r0 * HH + c;
        size_t a1 = rowBase + (size_t)(t_r0 + 8) * HH + c;
        float2 o0 = *(const float2*)&g_g3[a0];
        float2 o1 = *(const float2*)&g_g3[a1];
        *(float2*)&g_h[a0] = make_float2(numO[nt][0]*inv0*o0.x,
                                         numO[nt][1]*inv0*o0.y);
        *(float2*)&g_h[a1] = make_float2(numO[nt][2]*inv1*o1.x,
                                         numO[nt][3]*inv1*o1.y);
    }
}

// ---------------- sLSTM recurrent scan (512 thr, fast math) --------------------
__global__ void __launch_bounds__(512) slstm_scan(const float* __restrict__ Rz,
                                                  const float* __restrict__ Ri,
                                                  const float* __restrict__ Rf,
                                                  const float* __restrict__ Ro) {
    int b  = blockIdx.x >> 2;
    int nh = blockIdx.x & 3;
    int t  = threadIdx.x;
    int g    = t >> 7;
    int rem  = t & 127;
    int e    = rem >> 1;
    int half = rem & 1;

    const float* Rg = ((g==0) ? Rz : (g==1) ? Ri : (g==2) ? Rf : Ro) + nh*DHH*DHH;
    float Rcol[32];
    #pragma unroll
    for (int d = 0; d < 32; d++) Rcol[d] = Rg[(half*32 + d)*64 + e];

    const float* gb = (g==0) ? g_g0 : (g==1) ? g_g1 : (g==2) ? g_g2 : g_g3;
    const float* gp = gb + (size_t)(b*TT)*HH + nh*DHH + e;

    __shared__ __align__(16) float sh[64];
    __shared__ float spre[4][64];
    if (t < 64) sh[t] = 0.f;
    float c = 0.f, n = 0.f, m = 0.f;

    float pre = (half == 0) ? gp[0] : 0.f;
    __syncthreads();

    for (int tt = 0; tt < TT; tt++) {
        const float* shh = sh + half*32;
        float r0 = 0.f, r1 = 0.f, r2 = 0.f, r3 = 0.f;
        #pragma unroll
        for (int d4 = 0; d4 < 8; d4++) {
            float4 h4 = *(const float4*)&shh[d4*4];
            r0 = fmaf(h4.x, Rcol[d4*4+0], r0);
            r1 = fmaf(h4.y, Rcol[d4*4+1], r1);
            r2 = fmaf(h4.z, Rcol[d4*4+2], r2);
            r3 = fmaf(h4.w, Rcol[d4*4+3], r3);
        }
        float r = (r0 + r1) + (r2 + r3);
        r += __shfl_xor_sync(0xffffffffu, r, 1);
        if (half == 0) {
            float p = pre + r;
            if (g == 0) {
                p = 1.f - __fdividef(2.f, __expf(2.f*p) + 1.f);
            } else if (g == 3) {
                p = __fdividef(1.f, 1.f + __expf(-p));
            }
            spre[g][e] = p;
        }
        __syncthreads();

        if (half == 0 && tt + 1 < TT) pre = gp[(size_t)(tt+1) * HH];

        if (t < 64) {
            float z   = spre[0][t];
            float ipp = spre[1][t];
            float fpp = spre[2][t];
            float o   = spre[3][t];
            float mn  = fmaxf(fpp + m, ipp);
            float i_s = __expf(ipp - mn);
            float f_s = __expf(fpp + m - mn);
            m = mn;
            c = fmaf(f_s, c, i_s * z);
            n = fmaf(f_s, n, i_s);
            float h = o * __fdividef(c, n);
            sh[t] = h;
            g_h[(size_t)(b*TT + tt)*HH + nh*DHH + t] = h;
        }
        __syncthreads();
    }
}

// ---------------- head ----------------------------------------------------------
__global__ void final_kernel(const float* __restrict__ fcW,
                             const float* __restrict__ fcb,
                             float* __restrict__ out) {
    int bI = blockIdx.x, t = threadIdx.x;
    float v = g_x[(size_t)(bI*TT + TT-1)*DD + t] * fcW[t];
    #pragma unroll
    for (int off = 16; off; off >>= 1)
        v += __shfl_xor_sync(0xffffffffu, v, off);
    __shared__ float a[8];
    if ((t & 31) == 0) a[t >> 5] = v;
    __syncthreads();
    if (t == 0) {
        float s = 0.f;
        #pragma unroll
        for (int i = 0; i < 8; i++) s += a[i];
        out[bI] = s + fcb[0];
    }
}

// ---------------- launch sequence ----------------------------------------------
extern "C" void kernel_launch(void* const* d_in, const int* in_sizes, int n_in,
                              void* d_out, int out_size) {
    const float* X      = (const float*)d_in[0];
    const int*   dyad   = (const int*)  d_in[1];
    const float* embed  = (const float*)d_in[2];
    const float* m_ln_g = (const float*)d_in[3];
    const float* m_ln_b = (const float*)d_in[4];
    const float* m_Wq   = (const float*)d_in[5];
    const float* m_Wk   = (const float*)d_in[6];
    const float* m_Wv   = (const float*)d_in[7];
    const float* m_Wi   = (const float*)d_in[8];
    const float* m_Wf   = (const float*)d_in[9];
    const float* m_bi   = (const float*)d_in[10];
    const float* m_bf   = (const float*)d_in[11];
    const float* m_Wo   = (const float*)d_in[12];
    const float* m_Wp   = (const float*)d_in[13];
    const float* s_ln_g = (const float*)d_in[14];
    const float* s_ln_b = (const float*)d_in[15];
    const float* s_Wz   = (const float*)d_in[16];
    const float* s_Wi   = (const float*)d_in[17];
    const float* s_Wf   = (const float*)d_in[18];
    const float* s_Wo   = (const float*)d_in[19];
    const float* s_Rz   = (const float*)d_in[20];
    const float* s_Ri   = (const float*)d_in[21];
    const float* s_Rf   = (const float*)d_in[22];
    const float* s_Ro   = (const float*)d_in[23];
    const float* s_Wp   = (const float*)d_in[24];
    const float* fc_W   = (const float*)d_in[25];
    const float* fc_b   = (const float*)d_in[26];
    float* out = (float*)d_out;

    static int attr_set = 0;
    if (!attr_set) {
        cudaFuncSetAttribute(mlstm_attn,
                             cudaFuncAttributeMaxDynamicSharedMemorySize,
                             ATTN_SMEM);
        cudaFuncSetAttribute(gemm_mma,
                             cudaFuncAttributeMaxDynamicSharedMemorySize,
                             GEMM_SMEM);
        cudaFuncSetAttribute(gemm_res64,
                             cudaFuncAttributeMaxDynamicSharedMemorySize,
                             GEMM2_SMEM);
        attr_set = 1;
    }

    dim3 gGate(8, ROWS/128);
    dim3 gRes (4, ROWS/128);

    build_ln<<<ROWS, 256>>>(X, dyad, embed, m_ln_g, m_ln_b);

    // ---- mLSTM layer 0 ----
    gemm_mma<<<gGate, 256, GEMM_SMEM>>>(SEL_XN, m_Wq, m_Wk, m_Wv, m_Wo, 0);
    gates_pre<<<BB*NHH, 256>>>(m_Wi, m_Wf, m_bi, m_bf);
    mlstm_attn<<<512, 128, ATTN_SMEM>>>();
    gemm_res64<<<gRes, 256, GEMM2_SMEM>>>(m_Wp);

    // ---- sLSTM layer ----
    ln_kernel<<<ROWS, 256>>>(s_ln_g, s_ln_b);
    gemm_mma<<<gGate, 256, GEMM_SMEM>>>(SEL_XN, s_Wz, s_Wi, s_Wf, s_Wo, 1);
    slstm_scan<<<BB*NHH, 512>>>(s_Rz, s_Ri, s_Rf, s_Ro);
    gemm_res64<<<gRes, 256, GEMM2_SMEM>>>(s_Wp);

    // ---- mLSTM layer 1 ----
    ln_kernel<<<ROWS, 256>>>(m_ln_g + DD, m_ln_b + DD);
    gemm_mma<<<gGate, 256, GEMM_SMEM>>>(SEL_XN, m_Wq + DD*HH, m_Wk + DD*HH,
                                        m_Wv + DD*HH, m_Wo + DD*HH, 0);
    gates_pre<<<BB*NHH, 256>>>(m_Wi + DD*NHH, m_Wf + DD*NHH,
                               m_bi + NHH, m_bf + NHH);
    mlstm_attn<<<512, 128, ATTN_SMEM>>>();
    gemm_res64<<<gRes, 256, GEMM2_SMEM>>>(m_Wp + HH*DD);

    final_kernel<<<BB, 256>>>(fc_W, fc_b, out);
    (void)in_sizes; (void)n_in; (void)out_size;
}

// round 16
// speedup vs baseline: 1.0160x; 1.0160x over previous
#include <cuda_runtime.h>
#include <cstdint>

// Problem constants
#define BB   32
#define TT   256
#define FF   224
#define EE   32
#define NHH  4
#define DHH  64
#define DD   256
#define HH   256
#define ROWS (BB*TT)   // 8192

// ---------------- scratch (static device globals; no allocation) ------------
__device__ float g_x [ROWS*DD];
__device__ float g_xn[ROWS*DD];
__device__ float g_g0[ROWS*HH];
__device__ float g_g1[ROWS*HH];
__device__ float g_g2[ROWS*HH];
__device__ float g_g3[ROWS*HH];
__device__ float g_h [ROWS*HH];
__device__ float g_bs[BB*NHH*TT];
__device__ float g_Mt[BB*NHH*TT];

__device__ __forceinline__ float* bufsel(int s) {
    switch (s) {
        case 0: return g_x;
        case 1: return g_xn;
        default: return g_h;
    }
}
#define SEL_X  0
#define SEL_XN 1
#define SEL_H  2

__device__ __forceinline__ void cp16(void* s, const void* g) {
    uint32_t sa = (uint32_t)__cvta_generic_to_shared(s);
    asm volatile("cp.async.cg.shared.global [%0], [%1], 16;"
                 :: "r"(sa), "l"(g) : "memory");
}
#define CP_COMMIT() asm volatile("cp.async.commit_group;" ::: "memory")
#define CP_WAIT1()  asm volatile("cp.async.wait_group 1;" ::: "memory")
#define CP_WAIT0()  asm volatile("cp.async.wait_group 0;" ::: "memory")

// ---------------- input assembly + LayerNorm 0 --------------------------------
__global__ void build_ln(const float* __restrict__ X,
                         const int*   __restrict__ dyad,
                         const float* __restrict__ embed,
                         const float* __restrict__ gam,
                         const float* __restrict__ bet) {
    int row = blockIdx.x;
    int t   = threadIdx.x;
    int b   = row / TT;
    float v;
    if (t < FF) v = X[row*FF + t];
    else        v = embed[dyad[b]*EE + (t - FF)];
    g_x[row*DD + t] = v;

    float s = v, s2 = v*v;
    #pragma unroll
    for (int off = 16; off; off >>= 1) {
        s  += __shfl_xor_sync(0xffffffffu, s,  off);
        s2 += __shfl_xor_sync(0xffffffffu, s2, off);
    }
    __shared__ float a1[8], a2[8];
    __shared__ float smu, srs;
    if ((t & 31) == 0) { a1[t >> 5] = s; a2[t >> 5] = s2; }
    __syncthreads();
    if (t == 0) {
        float u = 0.f, u2 = 0.f;
        #pragma unroll
        for (int i = 0; i < 8; i++) { u += a1[i]; u2 += a2[i]; }
        float mu  = u  * (1.0f/DD);
        float var = u2 * (1.0f/DD) - mu*mu;
        smu = mu;
        srs = rsqrtf(var + 1e-5f);
    }
    __syncthreads();
    g_xn[row*DD + t] = (v - smu) * srs * gam[t] + bet[t];
}

// ---------------- LayerNorm ----------------------------------------------------
__global__ void ln_kernel(const float* __restrict__ gam,
                          const float* __restrict__ bet) {
    int row = blockIdx.x, t = threadIdx.x;
    float x  = g_x[row*DD + t];
    float s  = x, s2 = x*x;
    #pragma unroll
    for (int off = 16; off; off >>= 1) {
        s  += __shfl_xor_sync(0xffffffffu, s,  off);
        s2 += __shfl_xor_sync(0xffffffffu, s2, off);
    }
    __shared__ float a1[8], a2[8];
    __shared__ float smu, srs;
    if ((t & 31) == 0) { a1[t >> 5] = s; a2[t >> 5] = s2; }
    __syncthreads();
    if (t == 0) {
        float u = 0.f, u2 = 0.f;
        #pragma unroll
        for (int i = 0; i < 8; i++) { u += a1[i]; u2 += a2[i]; }
        float mu  = u  * (1.0f/DD);
        float var = u2 * (1.0f/DD) - mu*mu;
        smu = mu;
        srs = rsqrtf(var + 1e-5f);
    }
    __syncthreads();
    g_xn[row*DD + t] = (x - smu) * srs * gam[t] + bet[t];
}

// ---------------- tf32 mma helper ----------------------------------------------
__device__ __forceinline__ void mma_tf32(float (&d)[4],
                                         const uint32_t (&a)[4],
                                         const uint32_t (&b)[2]) {
    asm volatile(
        "mma.sync.aligned.m16n8k8.row.col.f32.tf32.tf32.f32 "
        "{%0,%1,%2,%3}, {%4,%5,%6,%7}, {%8,%9}, {%0,%1,%2,%3};"
        : "+f"(d[0]), "+f"(d[1]), "+f"(d[2]), "+f"(d[3])
        : "r"(a[0]), "r"(a[1]), "r"(a[2]), "r"(a[3]),
          "r"(b[0]), "r"(b[1]));
}

// ---------------- tf32 GEMM: 128x128 tile, BK=32, cp.async double buffer -------
#define BK   32
#define AST  36
#define BST  136
#define GEMM_SMEM ((2*128*AST + 2*BK*BST) * 4)

__global__ void __launch_bounds__(256, 2) gemm_mma(
    int aSel,
    const float* __restrict__ W0, const float* __restrict__ W1,
    const float* __restrict__ W2, const float* __restrict__ W3,
    int mode)
{
    extern __shared__ uint32_t smg[];
    uint32_t* smA = smg;
    uint32_t* smB = smg + 2*128*AST;

    int tid  = threadIdx.x;
    int wid  = tid >> 5;
    int lane = tid & 31;
    int grp  = lane >> 2;
    int tig  = lane & 3;

    int w  = blockIdx.x >> 1;
    int nt = blockIdx.x & 1;
    int colBase = nt * 128;
    int rowBase = blockIdx.y * 128;
    const float* Wsel = (w==0) ? W0 : (w==1) ? W1 : (w==2) ? W2 : W3;
    const float* A    = bufsel(aSel) + (size_t)rowBase * DD;

    int warpM = wid >> 1;
    int warpN = wid & 1;

    float acc[2][8][4];
    #pragma unroll
    for (int i = 0; i < 2; i++)
        #pragma unroll
        for (int j = 0; j < 8; j++)
            #pragma unroll
            for (int q = 0; q < 4; q++) acc[i][j][q] = 0.f;

    auto loadT = [&](int buf, int k0) {
        uint32_t* Ab = smA + buf*(128*AST);
        uint32_t* Bb = smB + buf*(BK*BST);
        #pragma unroll
        for (int i = 0; i < 4; i++) {
            int ch = tid + i*256;
            int r  = ch >> 3, cq = (ch & 7) * 4;
            cp16(Ab + r*AST + cq, A + (size_t)r*DD + k0 + cq);
        }
        #pragma unroll
        for (int i = 0; i < 4; i++) {
            int ch = tid + i*256;
            int rb = ch >> 5, cq = (ch & 31) * 4;
            cp16(Bb + rb*BST + cq, Wsel + (size_t)(k0 + rb)*HH + colBase + cq);
        }
    };

    loadT(0, 0);  CP_COMMIT();
    loadT(1, BK); CP_COMMIT();

    const int KI = DD / BK;
    #pragma unroll
    for (int i = 0; i < KI; i++) {
        CP_WAIT1();
        __syncthreads();
        int buf = i & 1;
        uint32_t* Ab = smA + buf*(128*AST);
        uint32_t* Bb = smB + buf*(BK*BST);

        #pragma unroll
        for (int ks = 0; ks < 4; ks++) {
            uint32_t afr[2][4];
            #pragma unroll
            for (int mt = 0; mt < 2; mt++) {
                int r = warpM*32 + mt*16 + grp;
                int c = ks*8 + tig;
                afr[mt][0] = Ab[r*AST + c];
                afr[mt][1] = Ab[(r+8)*AST + c];
                afr[mt][2] = Ab[r*AST + c + 4];
                afr[mt][3] = Ab[(r+8)*AST + c + 4];
            }
            uint32_t bfr[8][2];
            #pragma unroll
            for (int nt2 = 0; nt2 < 8; nt2++) {
                int c = warpN*64 + nt2*8 + grp;
                bfr[nt2][0] = Bb[(ks*8 + tig)*BST + c];
                bfr[nt2][1] = Bb[(ks*8 + tig + 4)*BST + c];
            }
            #pragma unroll
            for (int mt = 0; mt < 2; mt++)
                #pragma unroll
                for (int nt2 = 0; nt2 < 8; nt2++)
                    mma_tf32(acc[mt][nt2], afr[mt], bfr[nt2]);
        }
        __syncthreads();
        if (i + 2 < KI) loadT(buf, (i + 2) * BK);
        CP_COMMIT();
    }

    float* C = (w == 0) ? g_g0 : (w == 1) ? g_g1 : (w == 2) ? g_g2 : g_g3;
    bool scaleK = (mode == 0) && (w == 1);
    bool sig    = (mode == 0) && (w == 3);

    #pragma unroll
    for (int mt = 0; mt < 2; mt++) {
        #pragma unroll
        for (int nt2 = 0; nt2 < 8; nt2++) {
            float v[4] = {acc[mt][nt2][0], acc[mt][nt2][1],
                          acc[mt][nt2][2], acc[mt][nt2][3]};
            if (scaleK) {
                #pragma unroll
                for (int q = 0; q < 4; q++) v[q] *= 0.125f;
            } else if (sig) {
                #pragma unroll
                for (int q = 0; q < 4; q++)
                    v[q] = __fdividef(1.f, 1.f + __expf(-v[q]));
            }
            int r0 = rowBase + warpM*32 + mt*16 + grp;
            int c0 = colBase + warpN*64 + nt2*8 + tig*2;
            *(float2*)(C + (size_t)r0 * HH + c0)     = make_float2(v[0], v[1]);
            *(float2*)(C + (size_t)(r0+8) * HH + c0) = make_float2(v[2], v[3]);
        }
    }
}

// ---------------- res GEMM: 128x64 tile (256 CTAs), residual accumulate --------
#define BST2 72
#define GEMM2_SMEM ((2*128*AST + 2*BK*BST2) * 4)

__global__ void __launch_bounds__(256, 2) gemm_res64(const float* __restrict__ Wp)
{
    extern __shared__ uint32_t smg[];
    uint32_t* smA = smg;
    uint32_t* smB = smg + 2*128*AST;

    int tid  = threadIdx.x;
    int wid  = tid >> 5;
    int lane = tid & 31;
    int grp  = lane >> 2;
    int tig  = lane & 3;

    int colBase = blockIdx.x * 64;
    int rowBase = blockIdx.y * 128;
    const float* A = g_h + (size_t)rowBase * HH;

    int warpM = wid >> 1;
    int warpN = wid & 1;

    float acc[2][4][4];
    #pragma unroll
    for (int i = 0; i < 2; i++)
        #pragma unroll
        for (int j = 0; j < 4; j++)
            #pragma unroll
            for (int q = 0; q < 4; q++) acc[i][j][q] = 0.f;

    auto loadT = [&](int buf, int k0) {
        uint32_t* Ab = smA + buf*(128*AST);
        uint32_t* Bb = smB + buf*(BK*BST2);
        #pragma unroll
        for (int i = 0; i < 4; i++) {
            int ch = tid + i*256;
            int r  = ch >> 3, cq = (ch & 7) * 4;
            cp16(Ab + r*AST + cq, A + (size_t)r*HH + k0 + cq);
        }
        #pragma unroll
        for (int i = 0; i < 2; i++) {
            int ch = tid + i*256;
            int rb = ch >> 4, cq = (ch & 15) * 4;
            cp16(Bb + rb*BST2 + cq, Wp + (size_t)(k0 + rb)*DD + colBase + cq);
        }
    };

    loadT(0, 0);  CP_COMMIT();
    loadT(1, BK); CP_COMMIT();

    const int KI = HH / BK;
    #pragma unroll
    for (int i = 0; i < KI; i++) {
        CP_WAIT1();
        __syncthreads();
        int buf = i & 1;
        uint32_t* Ab = smA + buf*(128*AST);
        uint32_t* Bb = smB + buf*(BK*BST2);

        #pragma unroll
        for (int ks = 0; ks < 4; ks++) {
            uint32_t afr[2][4];
            #pragma unroll
            for (int mt = 0; mt < 2; mt++) {
                int r = warpM*32 + mt*16 + grp;
                int c = ks*8 + tig;
                afr[mt][0] = Ab[r*AST + c];
                afr[mt][1] = Ab[(r+8)*AST + c];
                afr[mt][2] = Ab[r*AST + c + 4];
                afr[mt][3] = Ab[(r+8)*AST + c + 4];
            }
            uint32_t bfr[4][2];
            #pragma unroll
            for (int nt2 = 0; nt2 < 4; nt2++) {
                int c = warpN*32 + nt2*8 + grp;
                bfr[nt2][0] = Bb[(ks*8 + tig)*BST2 + c];
                bfr[nt2][1] = Bb[(ks*8 + tig + 4)*BST2 + c];
            }
            #pragma unroll
            for (int mt = 0; mt < 2; mt++)
                #pragma unroll
                for (int nt2 = 0; nt2 < 4; nt2++)
                    mma_tf32(acc[mt][nt2], afr[mt], bfr[nt2]);
        }
        __syncthreads();
        if (i + 2 < KI) loadT(buf, (i + 2) * BK);
        CP_COMMIT();
    }

    #pragma unroll
    for (int mt = 0; mt < 2; mt++) {
        #pragma unroll
        for (int nt2 = 0; nt2 < 4; nt2++) {
            int r0 = rowBase + warpM*32 + mt*16 + grp;
            int c0 = colBase + warpN*32 + nt2*8 + tig*2;
            float* p0 = g_x + (size_t)r0 * DD + c0;
            float* p1 = g_x + (size_t)(r0+8) * DD + c0;
            float2 o0 = *(const float2*)p0;
            float2 o1 = *(const float2*)p1;
            o0.x += acc[mt][nt2][0]; o0.y += acc[mt][nt2][1];
            o1.x += acc[mt][nt2][2]; o1.y += acc[mt][nt2][3];
            *(float2*)p0 = o0;
            *(float2*)p1 = o1;
        }
    }
}

// ---------------- fused gate preact + decay precompute -----------------------
__global__ void __launch_bounds__(256) gates_pre(const float* __restrict__ Wi,
                                                 const float* __restrict__ Wf,
                                                 const float* __restrict__ bi,
                                                 const float* __restrict__ bf) {
    __shared__ float wi_s[256], wf_s[256];
    __shared__ float sx[256][33];
    __shared__ double wsum[8];
    __shared__ float  wmax[8];

    int bh = blockIdx.x;
    int b = bh >> 2, nh = bh & 3;
    int tid = threadIdx.x;
    int lane = tid & 31, wid = tid >> 5;

    wi_s[tid] = Wi[tid*NHH + nh];
    wf_s[tid] = Wf[tid*NHH + nh];

    float ip = 0.f, fp = 0.f;
    for (int kc = 0; kc < 8; kc++) {
        __syncthreads();
        #pragma unroll
        for (int j = 0; j < 32; j++) {
            int idx = j*256 + tid;
            int r = idx >> 5, c = idx & 31;
            sx[r][c] = g_xn[(size_t)(b*TT + r)*DD + kc*32 + c];
        }
        __syncthreads();
        #pragma unroll
        for (int c = 0; c < 32; c++) {
            float x = sx[tid][c];
            ip = fmaf(x, wi_s[kc*32 + c], ip);
            fp = fmaf(x, wf_s[kc*32 + c], fp);
        }
    }
    ip += bi[nh];
    fp += bf[nh];

    double v = (double)fp;
    #pragma unroll
    for (int off = 1; off < 32; off <<= 1) {
        double u = __shfl_up_sync(0xffffffffu, v, off);
        if (lane >= off) v += u;
    }
    if (lane == 31) wsum[wid] = v;
    __syncthreads();
    if (tid < 32) {
        double t = (tid < 8) ? wsum[tid] : 0.0;
        #pragma unroll
        for (int off = 1; off < 8; off <<= 1) {
            double u = __shfl_up_sync(0xffffffffu, t, off);
            if (lane >= off) t += u;
        }
        if (tid < 8) wsum[tid] = t;
    }
    __syncthreads();
    double cumF = v + ((wid > 0) ? wsum[wid-1] : 0.0);
    float bt = (float)((double)ip - cumF);

    float mv = bt;
    #pragma unroll
    for (int off = 1; off < 32; off <<= 1) {
        float u = __shfl_up_sync(0xffffffffu, mv, off);
        if (lane >= off) mv = fmaxf(mv, u);
    }
    if (lane == 31) wmax[wid] = mv;
    __syncthreads();
    if (tid < 32) {
        float t = (tid < 8) ? wmax[tid] : -3.0e38f;
        #pragma unroll
        for (int off = 1; off < 8; off <<= 1) {
            float u = __shfl_up_sync(0xffffffffu, t, off);
            if (lane >= off) t = fmaxf(t, u);
        }
        if (tid < 8) wmax[tid] = t;
    }
    __syncthreads();
    float Mv = mv;
    if (wid > 0) Mv = fmaxf(Mv, wmax[wid-1]);
    Mv = fmaxf(Mv, 0.f);

    g_bs[bh*TT + tid] = bt;
    g_Mt[bh*TT + tid] = Mv;
}

// ---------------- parallel mLSTM attention (split K/V commit overlap) ---------
// grid 512 linear, work-descending: rt = 3 - (bid>>7).
// K committed as its own group; S=Q@K^T + P-weights run while V streams in.
#define PST 68
#define ATTN_SMEM (4*64*PST*4)

__global__ void __launch_bounds__(128) mlstm_attn() {
    extern __shared__ uint32_t smattn[];
    uint32_t (*Qs)[PST] = (uint32_t(*)[PST])(smattn);
    uint32_t (*Ks)[PST] = (uint32_t(*)[PST])(smattn + 64*PST);
    uint32_t (*Vs)[PST] = (uint32_t(*)[PST])(smattn + 2*64*PST);
    uint32_t (*Ps)[PST] = (uint32_t(*)[PST])(smattn + 3*64*PST);
    __shared__ float sb[64];

    int bid = blockIdx.x;
    int rt  = 3 - (bid >> 7);
    int bh  = bid & 127;
    int b = bh >> 2, nh = bh & 3;
    int tid  = threadIdx.x;
    int w    = tid >> 5;
    int lane = tid & 31;
    int grp  = lane >> 2;
    int tig  = lane & 3;
    int t0 = rt * 64;

    size_t rowBase = (size_t)(b*TT) * HH + nh*DHH;

    #pragma unroll
    for (int i = 0; i < 8; i++) {
        int idx = i*128 + tid;
        int r = idx >> 4, c = (idx & 15) * 4;
        cp16(&Qs[r][c], &g_g0[rowBase + (size_t)(t0 + r)*HH + c]);
    }
    float mrow0 = g_Mt[bh*TT + t0 + 16*w + grp];
    float mrow1 = g_Mt[bh*TT + t0 + 16*w + grp + 8];

    float numO[8][4];
    #pragma unroll
    for (int j = 0; j < 8; j++)
        #pragma unroll
        for (int q = 0; q < 4; q++) numO[j][q] = 0.f;
    float dsp0 = 0.f, dsp1 = 0.f;

    for (int jt = 0; jt <= rt; jt++) {
        int s0 = jt * 64;
        __syncthreads();    // prior-iteration K/V/Q reads complete
        #pragma unroll
        for (int i = 0; i < 8; i++) {
            int idx = i*128 + tid;
            int r = idx >> 4, c = (idx & 15) * 4;
            cp16(&Ks[r][c], &g_g1[rowBase + (size_t)(s0 + r)*HH + c]);
        }
        CP_COMMIT();        // group A: Q (iter 0) + K
        #pragma unroll
        for (int i = 0; i < 8; i++) {
            int idx = i*128 + tid;
            int r = idx >> 4, c = (idx & 15) * 4;
            cp16(&Vs[r][c], &g_g2[rowBase + (size_t)(s0 + r)*HH + c]);
        }
        if (tid < 64) sb[tid] = g_bs[bh*TT + s0 + tid];
        CP_COMMIT();        // group B: V
        CP_WAIT1();         // K (and Q) resident; V still streaming
        __syncthreads();

        // S = Q @ K^T (V load overlaps this)
        float accS[8][4];
        #pragma unroll
        for (int j = 0; j < 8; j++)
            #pragma unroll
            for (int q = 0; q < 4; q++) accS[j][q] = 0.f;
        #pragma unroll
        for (int ks = 0; ks < 8; ks++) {
            uint32_t a[4];
            a[0] = Qs[16*w + grp    ][8*ks + tig];
            a[1] = Qs[16*w + grp + 8][8*ks + tig];
            a[2] = Qs[16*w + grp    ][8*ks + tig + 4];
            a[3] = Qs[16*w + grp + 8][8*ks + tig + 4];
            #pragma unroll
            for (int nt = 0; nt < 8; nt++) {
                uint32_t bb[2];
                bb[0] = Ks[8*nt + grp][8*ks + tig];
                bb[1] = Ks[8*nt + grp][8*ks + tig + 4];
                mma_tf32(accS[nt], a, bb);
            }
        }

        // P weights (still overlapping V load)
        int t_r0 = t0 + 16*w + grp;
        int t_r1 = t_r0 + 8;
        #pragma unroll
        for (int nt = 0; nt < 8; nt++) {
            int cl = nt*8 + tig*2;
            int s_c = s0 + cl;
            float b0 = sb[cl], b1 = sb[cl+1];
            float w00 = __expf(b0 - mrow0), w01 = __expf(b1 - mrow0);
            float w10 = __expf(b0 - mrow1), w11 = __expf(b1 - mrow1);
            if (jt == rt) {
                if (s_c     > t_r0) w00 = 0.f;
                if (s_c + 1 > t_r0) w01 = 0.f;
                if (s_c     > t_r1) w10 = 0.f;
                if (s_c + 1 > t_r1) w11 = 0.f;
            }
            float p00 = accS[nt][0]*w00, p01 = accS[nt][1]*w01;
            float p10 = accS[nt][2]*w10, p11 = accS[nt][3]*w11;
            dsp0 += p00 + p01;
            dsp1 += p10 + p11;
            Ps[16*w + grp    ][cl]   = __float_as_uint(p00);
            Ps[16*w + grp    ][cl+1] = __float_as_uint(p01);
            Ps[16*w + grp + 8][cl]   = __float_as_uint(p10);
            Ps[16*w + grp + 8][cl+1] = __float_as_uint(p11);
        }
        CP_WAIT0();         // own V copies done
        __syncthreads();    // all threads' V copies visible (also orders P? no—P warp-private)

        // numO += P @ V
        #pragma unroll
        for (int ks = 0; ks < 8; ks++) {
            uint32_t a[4];
            a[0] = Ps[16*w + grp    ][8*ks + tig];
            a[1] = Ps[16*w + grp + 8][8*ks + tig];
            a[2] = Ps[16*w + grp    ][8*ks + tig + 4];
            a[3] = Ps[16*w + grp + 8][8*ks + tig + 4];
            #pragma unroll
            for (int nt = 0; nt < 8; nt++) {
                uint32_t bb[2];
                bb[0] = Vs[8*ks + tig    ][8*nt + grp];
                bb[1] = Vs[8*ks + tig + 4][8*nt + grp];
                mma_tf32(numO[nt], a, bb);
            }
        }
    }

    dsp0 += __shfl_xor_sync(0xffffffffu, dsp0, 1);
    dsp0 += __shfl_xor_sync(0xffffffffu, dsp0, 2);
    dsp1 += __shfl_xor_sync(0xffffffffu, dsp1, 1);
    dsp1 += __shfl_xor_sync(0xffffffffu, dsp1, 2);
    float inv0 = __fdividef(1.0f, fmaxf(fabsf(dsp0), 1.0f));
    float inv1 = __fdividef(1.0f, fmaxf(fabsf(dsp1), 1.0f));

    int t_r0 = t0 + 16*w + grp;
    #pragma unroll
    for (int nt = 0; nt < 8; nt++) {
        int c = nt*8 + tig*2;
        size_t a0 = rowBase + (size_t)t_r0 * HH + c;
        size_t a1 = rowBase + (size_t)(t_r0 + 8) * HH + c;
        float2 o0 = *(const float2*)&g_g3[a0];
        float2 o1 = *(const float2*)&g_g3[a1];
        *(float2*)&g_h[a0] = make_float2(numO[nt][0]*inv0*o0.x,
                                         numO[nt][1]*inv0*o0.y);
        *(float2*)&g_h[a1] = make_float2(numO[nt][2]*inv1*o1.x,
                                         numO[nt][3]*inv1*o1.y);
    }
}

// ---------------- sLSTM recurrent scan (512 thr, fast math) --------------------
__global__ void __launch_bounds__(512) slstm_scan(const float* __restrict__ Rz,
                                                  const float* __restrict__ Ri,
                                                  const float* __restrict__ Rf,
                                                  const float* __restrict__ Ro) {
    int b  = blockIdx.x >> 2;
    int nh = blockIdx.x & 3;
    int t  = threadIdx.x;
    int g    = t >> 7;
    int rem  = t & 127;
    int e    = rem >> 1;
    int half = rem & 1;

    const float* Rg = ((g==0) ? Rz : (g==1) ? Ri : (g==2) ? Rf : Ro) + nh*DHH*DHH;
    float Rcol[32];
    #pragma unroll
    for (int d = 0; d < 32; d++) Rcol[d] = Rg[(half*32 + d)*64 + e];

    const float* gb = (g==0) ? g_g0 : (g==1) ? g_g1 : (g==2) ? g_g2 : g_g3;
    const float* gp = gb + (size_t)(b*TT)*HH + nh*DHH + e;

    __shared__ __align__(16) float sh[64];
    __shared__ float spre[4][64];
    if (t < 64) sh[t] = 0.f;
    float c = 0.f, n = 0.f, m = 0.f;

    float pre = (half == 0) ? gp[0] : 0.f;
    __syncthreads();

    for (int tt = 0; tt < TT; tt++) {
        const float* shh = sh + half*32;
        float r0 = 0.f, r1 = 0.f, r2 = 0.f, r3 = 0.f;
        #pragma unroll
        for (int d4 = 0; d4 < 8; d4++) {
            float4 h4 = *(const float4*)&shh[d4*4];
            r0 = fmaf(h4.x, Rcol[d4*4+0], r0);
            r1 = fmaf(h4.y, Rcol[d4*4+1], r1);
            r2 = fmaf(h4.z, Rcol[d4*4+2], r2);
            r3 = fmaf(h4.w, Rcol[d4*4+3], r3);
        }
        float r = (r0 + r1) + (r2 + r3);
        r += __shfl_xor_sync(0xffffffffu, r, 1);
        if (half == 0) {
            float p = pre + r;
            if (g == 0) {
                p = 1.f - __fdividef(2.f, __expf(2.f*p) + 1.f);
            } else if (g == 3) {
                p = __fdividef(1.f, 1.f + __expf(-p));
            }
            spre[g][e] = p;
        }
        __syncthreads();

        if (half == 0 && tt + 1 < TT) pre = gp[(size_t)(tt+1) * HH];

        if (t < 64) {
            float z   = spre[0][t];
            float ipp = spre[1][t];
            float fpp = spre[2][t];
            float o   = spre[3][t];
            float mn  = fmaxf(fpp + m, ipp);
            float i_s = __expf(ipp - mn);
            float f_s = __expf(fpp + m - mn);
            m = mn;
            c = fmaf(f_s, c, i_s * z);
            n = fmaf(f_s, n, i_s);
            float h = o * __fdividef(c, n);
            sh[t] = h;
            g_h[(size_t)(b*TT + tt)*HH + nh*DHH + t] = h;
        }
        __syncthreads();
    }
}

// ---------------- head ----------------------------------------------------------
__global__ void final_kernel(const float* __restrict__ fcW,
                             const float* __restrict__ fcb,
                             float* __restrict__ out) {
    int bI = blockIdx.x, t = threadIdx.x;
    float v = g_x[(size_t)(bI*TT + TT-1)*DD + t] * fcW[t];
    #pragma unroll
    for (int off = 16; off; off >>= 1)
        v += __shfl_xor_sync(0xffffffffu, v, off);
    __shared__ float a[8];
    if ((t & 31) == 0) a[t >> 5] = v;
    __syncthreads();
    if (t == 0) {
        float s = 0.f;
        #pragma unroll
        for (int i = 0; i < 8; i++) s += a[i];
        out[bI] = s + fcb[0];
    }
}

// ---------------- launch sequence ----------------------------------------------
extern "C" void kernel_launch(void* const* d_in, const int* in_sizes, int n_in,
                              void* d_out, int out_size) {
    const float* X      = (const float*)d_in[0];
    const int*   dyad   = (const int*)  d_in[1];
    const float* embed  = (const float*)d_in[2];
    const float* m_ln_g = (const float*)d_in[3];
    const float* m_ln_b = (const float*)d_in[4];
    const float* m_Wq   = (const float*)d_in[5];
    const float* m_Wk   = (const float*)d_in[6];
    const float* m_Wv   = (const float*)d_in[7];
    const float* m_Wi   = (const float*)d_in[8];
    const float* m_Wf   = (const float*)d_in[9];
    const float* m_bi   = (const float*)d_in[10];
    const float* m_bf   = (const float*)d_in[11];
    const float* m_Wo   = (const float*)d_in[12];
    const float* m_Wp   = (const float*)d_in[13];
    const float* s_ln_g = (const float*)d_in[14];
    const float* s_ln_b = (const float*)d_in[15];
    const float* s_Wz   = (const float*)d_in[16];
    const float* s_Wi   = (const float*)d_in[17];
    const float* s_Wf   = (const float*)d_in[18];
    const float* s_Wo   = (const float*)d_in[19];
    const float* s_Rz   = (const float*)d_in[20];
    const float* s_Ri   = (const float*)d_in[21];
    const float* s_Rf   = (const float*)d_in[22];
    const float* s_Ro   = (const float*)d_in[23];
    const float* s_Wp   = (const float*)d_in[24];
    const float* fc_W   = (const float*)d_in[25];
    const float* fc_b   = (const float*)d_in[26];
    float* out = (float*)d_out;

    static int attr_set = 0;
    if (!attr_set) {
        cudaFuncSetAttribute(mlstm_attn,
                             cudaFuncAttributeMaxDynamicSharedMemorySize,
                             ATTN_SMEM);
        cudaFuncSetAttribute(gemm_mma,
                             cudaFuncAttributeMaxDynamicSharedMemorySize,
                             GEMM_SMEM);
        cudaFuncSetAttribute(gemm_res64,
                             cudaFuncAttributeMaxDynamicSharedMemorySize,
                             GEMM2_SMEM);
        attr_set = 1;
    }

    dim3 gGate(8, ROWS/128);
    dim3 gRes (4, ROWS/128);

    build_ln<<<ROWS, 256>>>(X, dyad, embed, m_ln_g, m_ln_b);

    // ---- mLSTM layer 0 ----
    gemm_mma<<<gGate, 256, GEMM_SMEM>>>(SEL_XN, m_Wq, m_Wk, m_Wv, m_Wo, 0);
    gates_pre<<<BB*NHH, 256>>>(m_Wi, m_Wf, m_bi, m_bf);
    mlstm_attn<<<512, 128, ATTN_SMEM>>>();
    gemm_res64<<<gRes, 256, GEMM2_SMEM>>>(m_Wp);

    // ---- sLSTM layer ----
    ln_kernel<<<ROWS, 256>>>(s_ln_g, s_ln_b);
    gemm_mma<<<gGate, 256, GEMM_SMEM>>>(SEL_XN, s_Wz, s_Wi, s_Wf, s_Wo, 1);
    slstm_scan<<<BB*NHH, 512>>>(s_Rz, s_Ri, s_Rf, s_Ro);
    gemm_res64<<<gRes, 256, GEMM2_SMEM>>>(s_Wp);

    // ---- mLSTM layer 1 ----
    ln_kernel<<<ROWS, 256>>>(m_ln_g + DD, m_ln_b + DD);
    gemm_mma<<<gGate, 256, GEMM_SMEM>>>(SEL_XN, m_Wq + DD*HH, m_Wk + DD*HH,
                                        m_Wv + DD*HH, m_Wo + DD*HH, 0);
    gates_pre<<<BB*NHH, 256>>>(m_Wi + DD*NHH, m_Wf + DD*NHH,
                               m_bi + NHH, m_bf + NHH);
    mlstm_attn<<<512, 128, ATTN_SMEM>>>();
    gemm_res64<<<gRes, 256, GEMM2_SMEM>>>(m_Wp + HH*DD);

    final_kernel<<<BB, 256>>>(fc_W, fc_b, out);
    (void)in_sizes; (void)n_in; (void)out_size;
}

// round 17
// speedup vs baseline: 1.0338x; 1.0175x over previous
#include <cuda_runtime.h>
#include <cstdint>

// Problem constants
#define BB   32
#define TT   256
#define FF   224
#define EE   32
#define NHH  4
#define DHH  64
#define DD   256
#define HH   256
#define ROWS (BB*TT)   // 8192

// ---------------- scratch (static device globals; no allocation) ------------
__device__ float g_x [ROWS*DD];
__device__ float g_xn[ROWS*DD];
__device__ float g_g0[ROWS*HH];
__device__ float g_g1[ROWS*HH];
__device__ float g_g2[ROWS*HH];
__device__ float g_g3[ROWS*HH];
__device__ float g_h [ROWS*HH];
__device__ float g_bs[BB*NHH*TT];
__device__ float g_Mt[BB*NHH*TT];

__device__ __forceinline__ float* bufsel(int s) {
    switch (s) {
        case 0: return g_x;
        case 1: return g_xn;
        default: return g_h;
    }
}
#define SEL_X  0
#define SEL_XN 1
#define SEL_H  2

__device__ __forceinline__ void cp16(void* s, const void* g) {
    uint32_t sa = (uint32_t)__cvta_generic_to_shared(s);
    asm volatile("cp.async.cg.shared.global [%0], [%1], 16;"
                 :: "r"(sa), "l"(g) : "memory");
}
#define CP_COMMIT() asm volatile("cp.async.commit_group;" ::: "memory")
#define CP_WAIT1()  asm volatile("cp.async.wait_group 1;" ::: "memory")
#define CP_WAIT0()  asm volatile("cp.async.wait_group 0;" ::: "memory")

// ---------------- input assembly + LayerNorm 0 --------------------------------
__global__ void build_ln(const float* __restrict__ X,
                         const int*   __restrict__ dyad,
                         const float* __restrict__ embed,
                         const float* __restrict__ gam,
                         const float* __restrict__ bet) {
    int row = blockIdx.x;
    int t   = threadIdx.x;
    int b   = row / TT;
    float v;
    if (t < FF) v = X[row*FF + t];
    else        v = embed[dyad[b]*EE + (t - FF)];
    g_x[row*DD + t] = v;

    float s = v, s2 = v*v;
    #pragma unroll
    for (int off = 16; off; off >>= 1) {
        s  += __shfl_xor_sync(0xffffffffu, s,  off);
        s2 += __shfl_xor_sync(0xffffffffu, s2, off);
    }
    __shared__ float a1[8], a2[8];
    __shared__ float smu, srs;
    if ((t & 31) == 0) { a1[t >> 5] = s; a2[t >> 5] = s2; }
    __syncthreads();
    if (t == 0) {
        float u = 0.f, u2 = 0.f;
        #pragma unroll
        for (int i = 0; i < 8; i++) { u += a1[i]; u2 += a2[i]; }
        float mu  = u  * (1.0f/DD);
        float var = u2 * (1.0f/DD) - mu*mu;
        smu = mu;
        srs = rsqrtf(var + 1e-5f);
    }
    __syncthreads();
    g_xn[row*DD + t] = (v - smu) * srs * gam[t] + bet[t];
}

// ---------------- LayerNorm (warp per row; no block barriers) ------------------
__global__ void __launch_bounds__(256) ln_kernel(const float* __restrict__ gam,
                                                 const float* __restrict__ bet) {
    int wid  = threadIdx.x >> 5;
    int lane = threadIdx.x & 31;
    int row  = blockIdx.x * 8 + wid;

    const float* xr = g_x + (size_t)row * DD;
    int c0 = lane * 4;
    float4 v0 = *(const float4*)&xr[c0];
    float4 v1 = *(const float4*)&xr[c0 + 128];

    float s  = v0.x + v0.y + v0.z + v0.w + v1.x + v1.y + v1.z + v1.w;
    float s2 = v0.x*v0.x + v0.y*v0.y + v0.z*v0.z + v0.w*v0.w
             + v1.x*v1.x + v1.y*v1.y + v1.z*v1.z + v1.w*v1.w;
    #pragma unroll
    for (int off = 16; off; off >>= 1) {
        s  += __shfl_xor_sync(0xffffffffu, s,  off);
        s2 += __shfl_xor_sync(0xffffffffu, s2, off);
    }
    float mu  = s  * (1.0f/DD);
    float var = s2 * (1.0f/DD) - mu*mu;
    float rs  = rsqrtf(var + 1e-5f);

    float4 g0 = *(const float4*)&gam[c0];
    float4 g1 = *(const float4*)&gam[c0 + 128];
    float4 b0 = *(const float4*)&bet[c0];
    float4 b1 = *(const float4*)&bet[c0 + 128];
    float4 o0, o1;
    o0.x = (v0.x - mu)*rs*g0.x + b0.x;
    o0.y = (v0.y - mu)*rs*g0.y + b0.y;
    o0.z = (v0.z - mu)*rs*g0.z + b0.z;
    o0.w = (v0.w - mu)*rs*g0.w + b0.w;
    o1.x = (v1.x - mu)*rs*g1.x + b1.x;
    o1.y = (v1.y - mu)*rs*g1.y + b1.y;
    o1.z = (v1.z - mu)*rs*g1.z + b1.z;
    o1.w = (v1.w - mu)*rs*g1.w + b1.w;
    float* xo = g_xn + (size_t)row * DD;
    *(float4*)&xo[c0]       = o0;
    *(float4*)&xo[c0 + 128] = o1;
}

// ---------------- tf32 mma helper ----------------------------------------------
__device__ __forceinline__ void mma_tf32(float (&d)[4],
                                         const uint32_t (&a)[4],
                                         const uint32_t (&b)[2]) {
    asm volatile(
        "mma.sync.aligned.m16n8k8.row.col.f32.tf32.tf32.f32 "
        "{%0,%1,%2,%3}, {%4,%5,%6,%7}, {%8,%9}, {%0,%1,%2,%3};"
        : "+f"(d[0]), "+f"(d[1]), "+f"(d[2]), "+f"(d[3])
        : "r"(a[0]), "r"(a[1]), "r"(a[2]), "r"(a[3]),
          "r"(b[0]), "r"(b[1]));
}

// ---------------- tf32 GEMM: 128x128 tile, BK=32, cp.async double buffer -------
#define BK   32
#define AST  36
#define BST  136
#define GEMM_SMEM ((2*128*AST + 2*BK*BST) * 4)

__global__ void __launch_bounds__(256, 2) gemm_mma(
    int aSel,
    const float* __restrict__ W0, const float* __restrict__ W1,
    const float* __restrict__ W2, const float* __restrict__ W3,
    int mode)
{
    extern __shared__ uint32_t smg[];
    uint32_t* smA = smg;
    uint32_t* smB = smg + 2*128*AST;

    int tid  = threadIdx.x;
    int wid  = tid >> 5;
    int lane = tid & 31;
    int grp  = lane >> 2;
    int tig  = lane & 3;

    int w  = blockIdx.x >> 1;
    int nt = blockIdx.x & 1;
    int colBase = nt * 128;
    int rowBase = blockIdx.y * 128;
    const float* Wsel = (w==0) ? W0 : (w==1) ? W1 : (w==2) ? W2 : W3;
    const float* A    = bufsel(aSel) + (size_t)rowBase * DD;

    int warpM = wid >> 1;
    int warpN = wid & 1;

    float acc[2][8][4];
    #pragma unroll
    for (int i = 0; i < 2; i++)
        #pragma unroll
        for (int j = 0; j < 8; j++)
            #pragma unroll
            for (int q = 0; q < 4; q++) acc[i][j][q] = 0.f;

    auto loadT = [&](int buf, int k0) {
        uint32_t* Ab = smA + buf*(128*AST);
        uint32_t* Bb = smB + buf*(BK*BST);
        #pragma unroll
        for (int i = 0; i < 4; i++) {
            int ch = tid + i*256;
            int r  = ch >> 3, cq = (ch & 7) * 4;
            cp16(Ab + r*AST + cq, A + (size_t)r*DD + k0 + cq);
        }
        #pragma unroll
        for (int i = 0; i < 4; i++) {
            int ch = tid + i*256;
            int rb = ch >> 5, cq = (ch & 31) * 4;
            cp16(Bb + rb*BST + cq, Wsel + (size_t)(k0 + rb)*HH + colBase + cq);
        }
    };

    loadT(0, 0);  CP_COMMIT();
    loadT(1, BK); CP_COMMIT();

    const int KI = DD / BK;
    #pragma unroll
    for (int i = 0; i < KI; i++) {
        CP_WAIT1();
        __syncthreads();
        int buf = i & 1;
        uint32_t* Ab = smA + buf*(128*AST);
        uint32_t* Bb = smB + buf*(BK*BST);

        #pragma unroll
        for (int ks = 0; ks < 4; ks++) {
            uint32_t afr[2][4];
            #pragma unroll
            for (int mt = 0; mt < 2; mt++) {
                int r = warpM*32 + mt*16 + grp;
                int c = ks*8 + tig;
                afr[mt][0] = Ab[r*AST + c];
                afr[mt][1] = Ab[(r+8)*AST + c];
                afr[mt][2] = Ab[r*AST + c + 4];
                afr[mt][3] = Ab[(r+8)*AST + c + 4];
            }
            uint32_t bfr[8][2];
            #pragma unroll
            for (int nt2 = 0; nt2 < 8; nt2++) {
                int c = warpN*64 + nt2*8 + grp;
                bfr[nt2][0] = Bb[(ks*8 + tig)*BST + c];
                bfr[nt2][1] = Bb[(ks*8 + tig + 4)*BST + c];
            }
            #pragma unroll
            for (int mt = 0; mt < 2; mt++)
                #pragma unroll
                for (int nt2 = 0; nt2 < 8; nt2++)
                    mma_tf32(acc[mt][nt2], afr[mt], bfr[nt2]);
        }
        __syncthreads();
        if (i + 2 < KI) loadT(buf, (i + 2) * BK);
        CP_COMMIT();
    }

    float* C = (w == 0) ? g_g0 : (w == 1) ? g_g1 : (w == 2) ? g_g2 : g_g3;
    bool scaleK = (mode == 0) && (w == 1);
    bool sig    = (mode == 0) && (w == 3);

    #pragma unroll
    for (int mt = 0; mt < 2; mt++) {
        #pragma unroll
        for (int nt2 = 0; nt2 < 8; nt2++) {
            float v[4] = {acc[mt][nt2][0], acc[mt][nt2][1],
                          acc[mt][nt2][2], acc[mt][nt2][3]};
            if (scaleK) {
                #pragma unroll
                for (int q = 0; q < 4; q++) v[q] *= 0.125f;
            } else if (sig) {
                #pragma unroll
                for (int q = 0; q < 4; q++)
                    v[q] = __fdividef(1.f, 1.f + __expf(-v[q]));
            }
            int r0 = rowBase + warpM*32 + mt*16 + grp;
            int c0 = colBase + warpN*64 + nt2*8 + tig*2;
            *(float2*)(C + (size_t)r0 * HH + c0)     = make_float2(v[0], v[1]);
            *(float2*)(C + (size_t)(r0+8) * HH + c0) = make_float2(v[2], v[3]);
        }
    }
}

// ---------------- res GEMM: 128x64 tile (256 CTAs), residual accumulate --------
#define BST2 72
#define GEMM2_SMEM ((2*128*AST + 2*BK*BST2) * 4)

__global__ void __launch_bounds__(256, 2) gemm_res64(const float* __restrict__ Wp)
{
    extern __shared__ uint32_t smg[];
    uint32_t* smA = smg;
    uint32_t* smB = smg + 2*128*AST;

    int tid  = threadIdx.x;
    int wid  = tid >> 5;
    int lane = tid & 31;
    int grp  = lane >> 2;
    int tig  = lane & 3;

    int colBase = blockIdx.x * 64;
    int rowBase = blockIdx.y * 128;
    const float* A = g_h + (size_t)rowBase * HH;

    int warpM = wid >> 1;
    int warpN = wid & 1;

    float acc[2][4][4];
    #pragma unroll
    for (int i = 0; i < 2; i++)
        #pragma unroll
        for (int j = 0; j < 4; j++)
            #pragma unroll
            for (int q = 0; q < 4; q++) acc[i][j][q] = 0.f;

    auto loadT = [&](int buf, int k0) {
        uint32_t* Ab = smA + buf*(128*AST);
        uint32_t* Bb = smB + buf*(BK*BST2);
        #pragma unroll
        for (int i = 0; i < 4; i++) {
            int ch = tid + i*256;
            int r  = ch >> 3, cq = (ch & 7) * 4;
            cp16(Ab + r*AST + cq, A + (size_t)r*HH + k0 + cq);
        }
        #pragma unroll
        for (int i = 0; i < 2; i++) {
            int ch = tid + i*256;
            int rb = ch >> 4, cq = (ch & 15) * 4;
            cp16(Bb + rb*BST2 + cq, Wp + (size_t)(k0 + rb)*DD + colBase + cq);
        }
    };

    loadT(0, 0);  CP_COMMIT();
    loadT(1, BK); CP_COMMIT();

    const int KI = HH / BK;
    #pragma unroll
    for (int i = 0; i < KI; i++) {
        CP_WAIT1();
        __syncthreads();
        int buf = i & 1;
        uint32_t* Ab = smA + buf*(128*AST);
        uint32_t* Bb = smB + buf*(BK*BST2);

        #pragma unroll
        for (int ks = 0; ks < 4; ks++) {
            uint32_t afr[2][4];
            #pragma unroll
            for (int mt = 0; mt < 2; mt++) {
                int r = warpM*32 + mt*16 + grp;
                int c = ks*8 + tig;
                afr[mt][0] = Ab[r*AST + c];
                afr[mt][1] = Ab[(r+8)*AST + c];
                afr[mt][2] = Ab[r*AST + c + 4];
                afr[mt][3] = Ab[(r+8)*AST + c + 4];
            }
            uint32_t bfr[4][2];
            #pragma unroll
            for (int nt2 = 0; nt2 < 4; nt2++) {
                int c = warpN*32 + nt2*8 + grp;
                bfr[nt2][0] = Bb[(ks*8 + tig)*BST2 + c];
                bfr[nt2][1] = Bb[(ks*8 + tig + 4)*BST2 + c];
            }
            #pragma unroll
            for (int mt = 0; mt < 2; mt++)
                #pragma unroll
                for (int nt2 = 0; nt2 < 4; nt2++)
                    mma_tf32(acc[mt][nt2], afr[mt], bfr[nt2]);
        }
        __syncthreads();
        if (i + 2 < KI) loadT(buf, (i + 2) * BK);
        CP_COMMIT();
    }

    #pragma unroll
    for (int mt = 0; mt < 2; mt++) {
        #pragma unroll
        for (int nt2 = 0; nt2 < 4; nt2++) {
            int r0 = rowBase + warpM*32 + mt*16 + grp;
            int c0 = colBase + warpN*32 + nt2*8 + tig*2;
            float* p0 = g_x + (size_t)r0 * DD + c0;
            float* p1 = g_x + (size_t)(r0+8) * DD + c0;
            float2 o0 = *(const float2*)p0;
            float2 o1 = *(const float2*)p1;
            o0.x += acc[mt][nt2][0]; o0.y += acc[mt][nt2][1];
            o1.x += acc[mt][nt2][2]; o1.y += acc[mt][nt2][3];
            *(float2*)p0 = o0;
            *(float2*)p1 = o1;
        }
    }
}

// ---------------- fused gate preact + decay precompute -----------------------
__global__ void __launch_bounds__(256) gates_pre(const float* __restrict__ Wi,
                                                 const float* __restrict__ Wf,
                                                 const float* __restrict__ bi,
                                                 const float* __restrict__ bf) {
    __shared__ float wi_s[256], wf_s[256];
    __shared__ float sx[256][33];
    __shared__ double wsum[8];
    __shared__ float  wmax[8];

    int bh = blockIdx.x;
    int b = bh >> 2, nh = bh & 3;
    int tid = threadIdx.x;
    int lane = tid & 31, wid = tid >> 5;

    wi_s[tid] = Wi[tid*NHH + nh];
    wf_s[tid] = Wf[tid*NHH + nh];

    float ip = 0.f, fp = 0.f;
    for (int kc = 0; kc < 8; kc++) {
        __syncthreads();
        #pragma unroll
        for (int j = 0; j < 32; j++) {
            int idx = j*256 + tid;
            int r = idx >> 5, c = idx & 31;
            sx[r][c] = g_xn[(size_t)(b*TT + r)*DD + kc*32 + c];
        }
        __syncthreads();
        #pragma unroll
        for (int c = 0; c < 32; c++) {
            float x = sx[tid][c];
            ip = fmaf(x, wi_s[kc*32 + c], ip);
            fp = fmaf(x, wf_s[kc*32 + c], fp);
        }
    }
    ip += bi[nh];
    fp += bf[nh];

    double v = (double)fp;
    #pragma unroll
    for (int off = 1; off < 32; off <<= 1) {
        double u = __shfl_up_sync(0xffffffffu, v, off);
        if (lane >= off) v += u;
    }
    if (lane == 31) wsum[wid] = v;
    __syncthreads();
    if (tid < 32) {
        double t = (tid < 8) ? wsum[tid] : 0.0;
        #pragma unroll
        for (int off = 1; off < 8; off <<= 1) {
            double u = __shfl_up_sync(0xffffffffu, t, off);
            if (lane >= off) t += u;
        }
        if (tid < 8) wsum[tid] = t;
    }
    __syncthreads();
    double cumF = v + ((wid > 0) ? wsum[wid-1] : 0.0);
    float bt = (float)((double)ip - cumF);

    float mv = bt;
    #pragma unroll
    for (int off = 1; off < 32; off <<= 1) {
        float u = __shfl_up_sync(0xffffffffu, mv, off);
        if (lane >= off) mv = fmaxf(mv, u);
    }
    if (lane == 31) wmax[wid] = mv;
    __syncthreads();
    if (tid < 32) {
        float t = (tid < 8) ? wmax[tid] : -3.0e38f;
        #pragma unroll
        for (int off = 1; off < 8; off <<= 1) {
            float u = __shfl_up_sync(0xffffffffu, t, off);
            if (lane >= off) t = fmaxf(t, u);
        }
        if (tid < 8) wmax[tid] = t;
    }
    __syncthreads();
    float Mv = mv;
    if (wid > 0) Mv = fmaxf(Mv, wmax[wid-1]);
    Mv = fmaxf(Mv, 0.f);

    g_bs[bh*TT + tid] = bt;
    g_Mt[bh*TT + tid] = Mv;
}

// ---------------- parallel mLSTM attention (split K/V commit overlap) ---------
#define PST 68
#define ATTN_SMEM (4*64*PST*4)

__global__ void __launch_bounds__(128) mlstm_attn() {
    extern __shared__ uint32_t smattn[];
    uint32_t (*Qs)[PST] = (uint32_t(*)[PST])(smattn);
    uint32_t (*Ks)[PST] = (uint32_t(*)[PST])(smattn + 64*PST);
    uint32_t (*Vs)[PST] = (uint32_t(*)[PST])(smattn + 2*64*PST);
    uint32_t (*Ps)[PST] = (uint32_t(*)[PST])(smattn + 3*64*PST);
    __shared__ float sb[64];

    int bid = blockIdx.x;
    int rt  = 3 - (bid >> 7);
    int bh  = bid & 127;
    int b = bh >> 2, nh = bh & 3;
    int tid  = threadIdx.x;
    int w    = tid >> 5;
    int lane = tid & 31;
    int grp  = lane >> 2;
    int tig  = lane & 3;
    int t0 = rt * 64;

    size_t rowBase = (size_t)(b*TT) * HH + nh*DHH;

    #pragma unroll
    for (int i = 0; i < 8; i++) {
        int idx = i*128 + tid;
        int r = idx >> 4, c = (idx & 15) * 4;
        cp16(&Qs[r][c], &g_g0[rowBase + (size_t)(t0 + r)*HH + c]);
    }
    float mrow0 = g_Mt[bh*TT + t0 + 16*w + grp];
    float mrow1 = g_Mt[bh*TT + t0 + 16*w + grp + 8];

    float numO[8][4];
    #pragma unroll
    for (int j = 0; j < 8; j++)
        #pragma unroll
        for (int q = 0; q < 4; q++) numO[j][q] = 0.f;
    float dsp0 = 0.f, dsp1 = 0.f;

    for (int jt = 0; jt <= rt; jt++) {
        int s0 = jt * 64;
        __syncthreads();
        #pragma unroll
        for (int i = 0; i < 8; i++) {
            int idx = i*128 + tid;
            int r = idx >> 4, c = (idx & 15) * 4;
            cp16(&Ks[r][c], &g_g1[rowBase + (size_t)(s0 + r)*HH + c]);
        }
        CP_COMMIT();        // group A: Q (iter 0) + K
        #pragma unroll
        for (int i = 0; i < 8; i++) {
            int idx = i*128 + tid;
            int r = idx >> 4, c = (idx & 15) * 4;
            cp16(&Vs[r][c], &g_g2[rowBase + (size_t)(s0 + r)*HH + c]);
        }
        if (tid < 64) sb[tid] = g_bs[bh*TT + s0 + tid];
        CP_COMMIT();        // group B: V
        CP_WAIT1();         // K (and Q) resident; V still streaming
        __syncthreads();

        // S = Q @ K^T (V load overlaps this)
        float accS[8][4];
        #pragma unroll
        for (int j = 0; j < 8; j++)
            #pragma unroll
            for (int q = 0; q < 4; q++) accS[j][q] = 0.f;
        #pragma unroll
        for (int ks = 0; ks < 8; ks++) {
            uint32_t a[4];
            a[0] = Qs[16*w + grp    ][8*ks + tig];
            a[1] = Qs[16*w + grp + 8][8*ks + tig];
            a[2] = Qs[16*w + grp    ][8*ks + tig + 4];
            a[3] = Qs[16*w + grp + 8][8*ks + tig + 4];
            #pragma unroll
            for (int nt = 0; nt < 8; nt++) {
                uint32_t bb[2];
                bb[0] = Ks[8*nt + grp][8*ks + tig];
                bb[1] = Ks[8*nt + grp][8*ks + tig + 4];
                mma_tf32(accS[nt], a, bb);
            }
        }

        // P weights (still overlapping V load)
        int t_r0 = t0 + 16*w + grp;
        int t_r1 = t_r0 + 8;
        #pragma unroll
        for (int nt = 0; nt < 8; nt++) {
            int cl = nt*8 + tig*2;
            int s_c = s0 + cl;
            float b0 = sb[cl], b1 = sb[cl+1];
            float w00 = __expf(b0 - mrow0), w01 = __expf(b1 - mrow0);
            float w10 = __expf(b0 - mrow1), w11 = __expf(b1 - mrow1);
            if (jt == rt) {
                if (s_c     > t_r0) w00 = 0.f;
                if (s_c + 1 > t_r0) w01 = 0.f;
                if (s_c     > t_r1) w10 = 0.f;
                if (s_c + 1 > t_r1) w11 = 0.f;
            }
            float p00 = accS[nt][0]*w00, p01 = accS[nt][1]*w01;
            float p10 = accS[nt][2]*w10, p11 = accS[nt][3]*w11;
            dsp0 += p00 + p01;
            dsp1 += p10 + p11;
            Ps[16*w + grp    ][cl]   = __float_as_uint(p00);
            Ps[16*w + grp    ][cl+1] = __float_as_uint(p01);
            Ps[16*w + grp + 8][cl]   = __float_as_uint(p10);
            Ps[16*w + grp + 8][cl+1] = __float_as_uint(p11);
        }
        CP_WAIT0();         // V resident
        __syncthreads();

        // numO += P @ V
        #pragma unroll
        for (int ks = 0; ks < 8; ks++) {
            uint32_t a[4];
            a[0] = Ps[16*w + grp    ][8*ks + tig];
            a[1] = Ps[16*w + grp + 8][8*ks + tig];
            a[2] = Ps[16*w + grp    ][8*ks + tig + 4];
            a[3] = Ps[16*w + grp + 8][8*ks + tig + 4];
            #pragma unroll
            for (int nt = 0; nt < 8; nt++) {
                uint32_t bb[2];
                bb[0] = Vs[8*ks + tig    ][8*nt + grp];
                bb[1] = Vs[8*ks + tig + 4][8*nt + grp];
                mma_tf32(numO[nt], a, bb);
            }
        }
    }

    dsp0 += __shfl_xor_sync(0xffffffffu, dsp0, 1);
    dsp0 += __shfl_xor_sync(0xffffffffu, dsp0, 2);
    dsp1 += __shfl_xor_sync(0xffffffffu, dsp1, 1);
    dsp1 += __shfl_xor_sync(0xffffffffu, dsp1, 2);
    float inv0 = __fdividef(1.0f, fmaxf(fabsf(dsp0), 1.0f));
    float inv1 = __fdividef(1.0f, fmaxf(fabsf(dsp1), 1.0f));

    int t_r0 = t0 + 16*w + grp;
    #pragma unroll
    for (int nt = 0; nt < 8; nt++) {
        int c = nt*8 + tig*2;
        size_t a0 = rowBase + (size_t)t_r0 * HH + c;
        size_t a1 = rowBase + (size_t)(t_r0 + 8) * HH + c;
        float2 o0 = *(const float2*)&g_g3[a0];
        float2 o1 = *(const float2*)&g_g3[a1];
        *(float2*)&g_h[a0] = make_float2(numO[nt][0]*inv0*o0.x,
                                         numO[nt][1]*inv0*o0.y);
        *(float2*)&g_h[a1] = make_float2(numO[nt][2]*inv1*o1.x,
                                         numO[nt][3]*inv1*o1.y);
    }
}

// ---------------- sLSTM recurrent scan (512 thr, fast math) --------------------
__global__ void __launch_bounds__(512) slstm_scan(const float* __restrict__ Rz,
                                                  const float* __restrict__ Ri,
                                                  const float* __restrict__ Rf,
                                                  const float* __restrict__ Ro) {
    int b  = blockIdx.x >> 2;
    int nh = blockIdx.x & 3;
    int t  = threadIdx.x;
    int g    = t >> 7;
    int rem  = t & 127;
    int e    = rem >> 1;
    int half = rem & 1;

    const float* Rg = ((g==0) ? Rz : (g==1) ? Ri : (g==2) ? Rf : Ro) + nh*DHH*DHH;
    float Rcol[32];
    #pragma unroll
    for (int d = 0; d < 32; d++) Rcol[d] = Rg[(half*32 + d)*64 + e];

    const float* gb = (g==0) ? g_g0 : (g==1) ? g_g1 : (g==2) ? g_g2 : g_g3;
    const float* gp = gb + (size_t)(b*TT)*HH + nh*DHH + e;

    __shared__ __align__(16) float sh[64];
    __shared__ float spre[4][64];
    if (t < 64) sh[t] = 0.f;
    float c = 0.f, n = 0.f, m = 0.f;

    float pre = (half == 0) ? gp[0] : 0.f;
    __syncthreads();

    for (int tt = 0; tt < TT; tt++) {
        const float* shh = sh + half*32;
        float r0 = 0.f, r1 = 0.f, r2 = 0.f, r3 = 0.f;
        #pragma unroll
        for (int d4 = 0; d4 < 8; d4++) {
            float4 h4 = *(const float4*)&shh[d4*4];
            r0 = fmaf(h4.x, Rcol[d4*4+0], r0);
            r1 = fmaf(h4.y, Rcol[d4*4+1], r1);
            r2 = fmaf(h4.z, Rcol[d4*4+2], r2);
            r3 = fmaf(h4.w, Rcol[d4*4+3], r3);
        }
        float r = (r0 + r1) + (r2 + r3);
        r += __shfl_xor_sync(0xffffffffu, r, 1);
        if (half == 0) {
            float p = pre + r;
            if (g == 0) {
                p = 1.f - __fdividef(2.f, __expf(2.f*p) + 1.f);
            } else if (g == 3) {
                p = __fdividef(1.f, 1.f + __expf(-p));
            }
            spre[g][e] = p;
        }
        __syncthreads();

        if (half == 0 && tt + 1 < TT) pre = gp[(size_t)(tt+1) * HH];

        if (t < 64) {
            float z   = spre[0][t];
            float ipp = spre[1][t];
            float fpp = spre[2][t];
            float o   = spre[3][t];
            float mn  = fmaxf(fpp + m, ipp);
            float i_s = __expf(ipp - mn);
            float f_s = __expf(fpp + m - mn);
            m = mn;
            c = fmaf(f_s, c, i_s * z);
            n = fmaf(f_s, n, i_s);
            float h = o * __fdividef(c, n);
            sh[t] = h;
            g_h[(size_t)(b*TT + tt)*HH + nh*DHH + t] = h;
        }
        __syncthreads();
    }
}

// ---------------- head ----------------------------------------------------------
__global__ void final_kernel(const float* __restrict__ fcW,
                             const float* __restrict__ fcb,
                             float* __restrict__ out) {
    int bI = blockIdx.x, t = threadIdx.x;
    float v = g_x[(size_t)(bI*TT + TT-1)*DD + t] * fcW[t];
    #pragma unroll
    for (int off = 16; off; off >>= 1)
        v += __shfl_xor_sync(0xffffffffu, v, off);
    __shared__ float a[8];
    if ((t & 31) == 0) a[t >> 5] = v;
    __syncthreads();
    if (t == 0) {
        float s = 0.f;
        #pragma unroll
        for (int i = 0; i < 8; i++) s += a[i];
        out[bI] = s + fcb[0];
    }
}

// ---------------- launch sequence ----------------------------------------------
extern "C" void kernel_launch(void* const* d_in, const int* in_sizes, int n_in,
                              void* d_out, int out_size) {
    const float* X      = (const float*)d_in[0];
    const int*   dyad   = (const int*)  d_in[1];
    const float* embed  = (const float*)d_in[2];
    const float* m_ln_g = (const float*)d_in[3];
    const float* m_ln_b = (const float*)d_in[4];
    const float* m_Wq   = (const float*)d_in[5];
    const float* m_Wk   = (const float*)d_in[6];
    const float* m_Wv   = (const float*)d_in[7];
    const float* m_Wi   = (const float*)d_in[8];
    const float* m_Wf   = (const float*)d_in[9];
    const float* m_bi   = (const float*)d_in[10];
    const float* m_bf   = (const float*)d_in[11];
    const float* m_Wo   = (const float*)d_in[12];
    const float* m_Wp   = (const float*)d_in[13];
    const float* s_ln_g = (const float*)d_in[14];
    const float* s_ln_b = (const float*)d_in[15];
    const float* s_Wz   = (const float*)d_in[16];
    const float* s_Wi   = (const float*)d_in[17];
    const float* s_Wf   = (const float*)d_in[18];
    const float* s_Wo   = (const float*)d_in[19];
    const float* s_Rz   = (const float*)d_in[20];
    const float* s_Ri   = (const float*)d_in[21];
    const float* s_Rf   = (const float*)d_in[22];
    const float* s_Ro   = (const float*)d_in[23];
    const float* s_Wp   = (const float*)d_in[24];
    const float* fc_W   = (const float*)d_in[25];
    const float* fc_b   = (const float*)d_in[26];
    float* out = (float*)d_out;

    static int attr_set = 0;
    if (!attr_set) {
        cudaFuncSetAttribute(mlstm_attn,
                             cudaFuncAttributeMaxDynamicSharedMemorySize,
                             ATTN_SMEM);
        cudaFuncSetAttribute(gemm_mma,
                             cudaFuncAttributeMaxDynamicSharedMemorySize,
                             GEMM_SMEM);
        cudaFuncSetAttribute(gemm_res64,
                             cudaFuncAttributeMaxDynamicSharedMemorySize,
                             GEMM2_SMEM);
        attr_set = 1;
    }

    dim3 gGate(8, ROWS/128);
    dim3 gRes (4, ROWS/128);

    build_ln<<<ROWS, 256>>>(X, dyad, embed, m_ln_g, m_ln_b);

    // ---- mLSTM layer 0 ----
    gemm_mma<<<gGate, 256, GEMM_SMEM>>>(SEL_XN, m_Wq, m_Wk, m_Wv, m_Wo, 0);
    gates_pre<<<BB*NHH, 256>>>(m_Wi, m_Wf, m_bi, m_bf);
    mlstm_attn<<<512, 128, ATTN_SMEM>>>();
    gemm_res64<<<gRes, 256, GEMM2_SMEM>>>(m_Wp);

    // ---- sLSTM layer ----
    ln_kernel<<<ROWS/8, 256>>>(s_ln_g, s_ln_b);
    gemm_mma<<<gGate, 256, GEMM_SMEM>>>(SEL_XN, s_Wz, s_Wi, s_Wf, s_Wo, 1);
    slstm_scan<<<BB*NHH, 512>>>(s_Rz, s_Ri, s_Rf, s_Ro);
    gemm_res64<<<gRes, 256, GEMM2_SMEM>>>(s_Wp);

    // ---- mLSTM layer 1 ----
    ln_kernel<<<ROWS/8, 256>>>(m_ln_g + DD, m_ln_b + DD);
    gemm_mma<<<gGate, 256, GEMM_SMEM>>>(SEL_XN, m_Wq + DD*HH, m_Wk + DD*HH,
                                        m_Wv + DD*HH, m_Wo + DD*HH, 0);
    gates_pre<<<BB*NHH, 256>>>(m_Wi + DD*NHH, m_Wf + DD*NHH,
                               m_bi + NHH, m_bf + NHH);
    mlstm_attn<<<512, 128, ATTN_SMEM>>>();
    gemm_res64<<<gRes, 256, GEMM2_SMEM>>>(m_Wp + HH*DD);

    final_kernel<<<BB, 256>>>(fc_W, fc_b, out);
    (void)in_sizes; (void)n_in; (void)out_size;
}